// round 8
// baseline (speedup 1.0000x reference)
#include <cuda_runtime.h>
#include <math.h>

// VectorQuantizer: inputs [16,4096,64] f32, weight [1024,64] f32.
// Output layout (f32): [loss(1) | quantized(65536*64) | perplexity(1) | indices(65536)]
// out+1 only 4-byte aligned -> scalar (coalesced) stores into out_q.
//
// Mapping: lane pair (L, L^16) covers the SAME 2 tokens, each lane owning half
// of the 64 dims. Partial dots combined by one shfl.bfly+add (commutative ->
// identical on both lanes). Doubles warp count to 2048 and halves x-register
// footprint vs the Tt=2 full-dim kernel.

#define N_TOK   65536
#define DIM     64
#define HDIM    32                      // dims per lane
#define NCODE   1024
#define CHUNK   64                      // codes staged in smem per iteration
#define NCHUNK  (NCODE / CHUNK)         // 16
#define TPB     128                     // 4 warps
#define TOKB    128                     // tokens per block (32 per warp)
#define NBLK    (N_TOK / TOKB)          // 512

__device__ __align__(16) float g_wnorm[NCODE * DIM];
__device__ float g_wsq[NCODE];
__device__ int   g_counts[NCODE];
__device__ float g_partials[NBLK];
__device__ unsigned g_done;

#define FFMA2(acc, a, b) \
    asm("fma.rn.f32x2 %0, %1, %2, %0;" : "+l"(acc) : "l"(a), "l"(b))
#define MUL2(d, a, b) \
    asm("mul.rn.f32x2 %0, %1, %2;" : "=l"(d) : "l"(a), "l"(b))
#define PACK2(d, lo, hi) \
    asm("mov.b64 %0, {%1,%2};" : "=l"(d) : "f"(lo), "f"(hi))

__device__ __forceinline__ float f32x2_hsum(unsigned long long v) {
    float lo, hi;
    asm("mov.b64 {%0,%1}, %2;" : "=f"(lo), "=f"(hi) : "l"(v));
    return lo + hi;
}

// ---------------------------------------------------------------------------
// Kernel 1: prep — zero histogram/done, normalize codebook rows + wsq.
// ---------------------------------------------------------------------------
__global__ __launch_bounds__(128) void vq_prep(const float* __restrict__ w) {
    int r = blockIdx.x * 128 + threadIdx.x;
    if (r == 0) g_done = 0;
    if (r >= NCODE) return;
    g_counts[r] = 0;
    const float4* src = reinterpret_cast<const float4*>(w + (size_t)r * DIM);
    float v[DIM];
    float ss = 0.f;
#pragma unroll
    for (int i = 0; i < DIM / 4; i++) {
        float4 q = src[i];
        v[4*i+0] = q.x; v[4*i+1] = q.y; v[4*i+2] = q.z; v[4*i+3] = q.w;
        ss += q.x*q.x + q.y*q.y + q.z*q.z + q.w*q.w;
    }
    float inv = 1.0f / fmaxf(sqrtf(ss), 1e-12f);
    float sq = 0.f;
    float4* dst = reinterpret_cast<float4*>(g_wnorm + (size_t)r * DIM);
#pragma unroll
    for (int i = 0; i < DIM / 4; i++) {
        float4 q;
        q.x = v[4*i+0] * inv; q.y = v[4*i+1] * inv;
        q.z = v[4*i+2] * inv; q.w = v[4*i+3] * inv;
        sq += q.x*q.x + q.y*q.y + q.z*q.z + q.w*q.w;
        dst[i] = q;
    }
    g_wsq[r] = sq;
}

// ---------------------------------------------------------------------------
// Kernel 2: main.
// ---------------------------------------------------------------------------
__global__ __launch_bounds__(TPB, 4) void vq_main(const float* __restrict__ x_in,
                                                  float* __restrict__ out_q,
                                                  float* __restrict__ out_idx,
                                                  float* __restrict__ out_loss,
                                                  float* __restrict__ out_perp) {
    __shared__ __align__(16) float sh[CHUNK * DIM];   // 16 KB
    __shared__ float swsq[CHUNK];
    __shared__ int   sbi[TOKB];
    __shared__ float red[TPB];
    __shared__ bool  is_last;

    const int tid  = threadIdx.x;
    const int lane = tid & 31;
    const int warp = tid >> 5;
    const int tp   = lane & 15;     // token pair id within warp
    const int half = lane >> 4;     // which half of the dims this lane owns
    const int T0   = blockIdx.x * TOKB;
    const int t0   = T0 + warp * 32 + tp * 2;   // this pair's even token
    const int t1   = t0 + 1;

    // --- load half-dims of 2 tokens, normalize (norms via lane-pair shfl) ---
    unsigned long long xp0[HDIM / 2], xp1[HDIM / 2];   // 16 + 16 ull
    float xsq0, xsq1;
    {
        const float4* a4 = reinterpret_cast<const float4*>(x_in + (size_t)t0 * DIM + half * HDIM);
        const float4* b4 = reinterpret_cast<const float4*>(x_in + (size_t)t1 * DIM + half * HDIM);
        float ssa = 0.f, ssb = 0.f;
#pragma unroll
        for (int i = 0; i < HDIM / 4; i++) {   // 8
            float4 q = a4[i];
            ssa = fmaf(q.x, q.x, ssa); ssa = fmaf(q.y, q.y, ssa);
            ssa = fmaf(q.z, q.z, ssa); ssa = fmaf(q.w, q.w, ssa);
            PACK2(xp0[2*i],   q.x, q.y);
            PACK2(xp0[2*i+1], q.z, q.w);
            float4 r = b4[i];
            ssb = fmaf(r.x, r.x, ssb); ssb = fmaf(r.y, r.y, ssb);
            ssb = fmaf(r.z, r.z, ssb); ssb = fmaf(r.w, r.w, ssb);
            PACK2(xp1[2*i],   r.x, r.y);
            PACK2(xp1[2*i+1], r.z, r.w);
        }
        ssa += __shfl_xor_sync(0xffffffffu, ssa, 16);
        ssb += __shfl_xor_sync(0xffffffffu, ssb, 16);
        float inva = 1.0f / fmaxf(sqrtf(ssa), 1e-12f);
        float invb = 1.0f / fmaxf(sqrtf(ssb), 1e-12f);
        unsigned long long ia, ib, sa = 0ull, sb = 0ull;
        PACK2(ia, inva, inva);
        PACK2(ib, invb, invb);
#pragma unroll
        for (int i = 0; i < HDIM / 2; i++) {   // 16
            MUL2(xp0[i], xp0[i], ia);
            FFMA2(sa, xp0[i], xp0[i]);
            MUL2(xp1[i], xp1[i], ib);
            FFMA2(sb, xp1[i], xp1[i]);
        }
        float hx0 = f32x2_hsum(sa);
        float hx1 = f32x2_hsum(sb);
        xsq0 = hx0 + __shfl_xor_sync(0xffffffffu, hx0, 16);
        xsq1 = hx1 + __shfl_xor_sync(0xffffffffu, hx1, 16);
    }

    float bd0 = INFINITY, bd1 = INFINITY;
    int   bi0 = 0,        bi1 = 0;

    for (int ch = 0; ch < NCHUNK; ch++) {
        const int c0 = ch * CHUNK;
        __syncthreads();   // previous chunk's readers done before overwrite
        {
            const float4* src = reinterpret_cast<const float4*>(g_wnorm + (size_t)c0 * DIM);
            float4* dst = reinterpret_cast<float4*>(sh);
#pragma unroll
            for (int i = 0; i < (CHUNK * DIM / 4) / TPB; i++)   // 8
                dst[i * TPB + tid] = src[i * TPB + tid];
            if (tid < CHUNK) swsq[tid] = g_wsq[c0 + tid];
        }
        __syncthreads();

        for (int kk = 0; kk < CHUNK; kk += 4) {
            // this lane reads its half of 4 codes' rows: 2 distinct 16B addrs
            // per request (half 0 lanes broadcast, half 1 lanes broadcast).
            const ulonglong2* wb =
                reinterpret_cast<const ulonglong2*>(sh + kk * DIM + half * HDIM);
            unsigned long long a0 = 0ull, a1 = 0ull, a2 = 0ull, a3 = 0ull;
            unsigned long long a4_ = 0ull, a5 = 0ull, a6 = 0ull, a7 = 0ull;
#pragma unroll
            for (int j = 0; j < HDIM / 4; j++) {   // 8 iters: 4 LDS, 16 FFMA2
                ulonglong2 v0 = wb[j];
                ulonglong2 v1 = wb[16 + j];    // code stride = 64 f = 16 u2
                ulonglong2 v2 = wb[32 + j];
                ulonglong2 v3 = wb[48 + j];
                FFMA2(a0, xp0[2*j],   v0.x); FFMA2(a4_, xp1[2*j],   v0.x);
                FFMA2(a1, xp0[2*j],   v1.x); FFMA2(a5,  xp1[2*j],   v1.x);
                FFMA2(a2, xp0[2*j],   v2.x); FFMA2(a6,  xp1[2*j],   v2.x);
                FFMA2(a3, xp0[2*j],   v3.x); FFMA2(a7,  xp1[2*j],   v3.x);
                FFMA2(a0, xp0[2*j+1], v0.y); FFMA2(a4_, xp1[2*j+1], v0.y);
                FFMA2(a1, xp0[2*j+1], v1.y); FFMA2(a5,  xp1[2*j+1], v1.y);
                FFMA2(a2, xp0[2*j+1], v2.y); FFMA2(a6,  xp1[2*j+1], v2.y);
                FFMA2(a3, xp0[2*j+1], v3.y); FFMA2(a7,  xp1[2*j+1], v3.y);
            }
            // combine lane-pair halves (commutative add -> identical on both)
            float h0 = f32x2_hsum(a0),  h1 = f32x2_hsum(a1);
            float h2 = f32x2_hsum(a2),  h3 = f32x2_hsum(a3);
            float h4 = f32x2_hsum(a4_), h5 = f32x2_hsum(a5);
            float h6 = f32x2_hsum(a6),  h7 = f32x2_hsum(a7);
            h0 += __shfl_xor_sync(0xffffffffu, h0, 16);
            h1 += __shfl_xor_sync(0xffffffffu, h1, 16);
            h2 += __shfl_xor_sync(0xffffffffu, h2, 16);
            h3 += __shfl_xor_sync(0xffffffffu, h3, 16);
            h4 += __shfl_xor_sync(0xffffffffu, h4, 16);
            h5 += __shfl_xor_sync(0xffffffffu, h5, 16);
            h6 += __shfl_xor_sync(0xffffffffu, h6, 16);
            h7 += __shfl_xor_sync(0xffffffffu, h7, 16);
            float w0 = swsq[kk+0], w1 = swsq[kk+1], w2 = swsq[kk+2], w3 = swsq[kk+3];
            float s0 = fmaf(-2.0f, h0, w0);
            float s1 = fmaf(-2.0f, h1, w1);
            float s2 = fmaf(-2.0f, h2, w2);
            float s3 = fmaf(-2.0f, h3, w3);
            float s4 = fmaf(-2.0f, h4, w0);
            float s5 = fmaf(-2.0f, h5, w1);
            float s6 = fmaf(-2.0f, h6, w2);
            float s7 = fmaf(-2.0f, h7, w3);
            // strict < ascending code order == jnp.argmin first-min tiebreak
            if (s0 < bd0) { bd0 = s0; bi0 = c0 + kk + 0; }
            if (s1 < bd0) { bd0 = s1; bi0 = c0 + kk + 1; }
            if (s2 < bd0) { bd0 = s2; bi0 = c0 + kk + 2; }
            if (s3 < bd0) { bd0 = s3; bi0 = c0 + kk + 3; }
            if (s4 < bd1) { bd1 = s4; bi1 = c0 + kk + 0; }
            if (s5 < bd1) { bd1 = s5; bi1 = c0 + kk + 1; }
            if (s6 < bd1) { bd1 = s6; bi1 = c0 + kk + 2; }
            if (s7 < bd1) { bd1 = s7; bi1 = c0 + kk + 3; }
        }
    }

    // --- per-token results: only the half==0 lane of each pair commits ---
    float myloss = 0.f;
    if (half == 0) {
        int lt0 = warp * 32 + tp * 2;       // token index within block
        sbi[lt0]     = bi0;
        sbi[lt0 + 1] = bi1;
        out_idx[t0] = (float)bi0;
        out_idx[t1] = (float)bi1;
        atomicAdd(&g_counts[bi0], 1);
        atomicAdd(&g_counts[bi1], 1);
        myloss = (xsq0 + bd0) + (xsq1 + bd1);   // ||q-x||^2 = xsq + (wsq-2dot)
    }
    __syncthreads();

    // --- coalesced quantized gather/store (out_q only 4B-aligned -> scalar) ---
#pragma unroll
    for (int it = 0; it < (TOKB * DIM) / TPB; it++) {    // 64
        int f = it * TPB + tid;
        int tok = f >> 6, dlane = f & 63;
        out_q[(size_t)T0 * DIM + f] = g_wnorm[(size_t)sbi[tok] * DIM + dlane];
    }

    // --- deterministic per-block loss partial ---
    red[tid] = myloss;
    __syncthreads();
#pragma unroll
    for (int s = TPB / 2; s > 0; s >>= 1) {
        if (tid < s) red[tid] += red[tid + s];
        __syncthreads();
    }
    if (tid == 0) {
        g_partials[blockIdx.x] = red[0];
        __threadfence();
        unsigned v = atomicAdd(&g_done, 1u);
        is_last = (v == NBLK - 1);
    }
    __syncthreads();

    // --- last block: finalize loss + perplexity (fixed order, deterministic) ---
    if (is_last) {
        __threadfence();
        float e = 0.f;
#pragma unroll
        for (int j = 0; j < NCODE / TPB; j++) {          // 8
            int c = __ldcg(&g_counts[tid * (NCODE / TPB) + j]);
            float p = (float)c * (1.0f / (float)N_TOK);
            e += p * logf(p + 1e-10f);
        }
        red[tid] = e;
        __syncthreads();
#pragma unroll
        for (int s = TPB / 2; s > 0; s >>= 1) {
            if (tid < s) red[tid] += red[tid + s];
            __syncthreads();
        }
        if (tid == 0) *out_perp = expf(-red[0]);
        __syncthreads();

        float l = 0.f;
#pragma unroll
        for (int j = 0; j < NBLK / TPB; j++)             // 4
            l += __ldcg(&g_partials[tid * (NBLK / TPB) + j]);
        red[tid] = l;
        __syncthreads();
#pragma unroll
        for (int s = TPB / 2; s > 0; s >>= 1) {
            if (tid < s) red[tid] += red[tid + s];
            __syncthreads();
        }
        if (tid == 0)
            *out_loss = 1.25f * (red[0] / (float)((long long)N_TOK * DIM));
    }
}

// ---------------------------------------------------------------------------
extern "C" void kernel_launch(void* const* d_in, const int* in_sizes, int n_in,
                              void* d_out, int out_size) {
    const float* x = (const float*)d_in[0];
    const float* w = (const float*)d_in[1];
    if (n_in >= 2 && in_sizes[0] < in_sizes[1]) {
        x = (const float*)d_in[1];
        w = (const float*)d_in[0];
    }

    float* out = (float*)d_out;
    const long long ND = (long long)N_TOK * DIM;
    float* out_loss = out;
    float* out_q    = out + 1;
    float* out_perp = out + 1 + ND;
    float* out_idx  = out + 2 + ND;

    vq_prep<<<8, 128>>>(w);
    vq_main<<<NBLK, TPB>>>(x, out_q, out_idx, out_loss, out_perp);
}

// round 10
// speedup vs baseline: 1.7018x; 1.7018x over previous
#include <cuda_runtime.h>
#include <cuda_bf16.h>
#include <math.h>
#include <cstdint>

// VectorQuantizer via mma.sync (HMMA) bf16x3-split GEMM. No tcgen05 (harness
// compiles at compute_103, no 'a' features).
// inputs [16,4096,64] f32, weight [1024,64] f32.
// Output (f32): [loss(1) | quantized(65536*64) | perplexity(1) | indices(65536)]
// out+1 only 4B-aligned -> scalar stores into out_q.

#define N_TOK   65536
#define DIM     64
#define NCODE   1024
#define TPB     128
#define TOKB    64
#define NBLK    (N_TOK / TOKB)     // 1024
#define CCH     64                 // codes per chunk
#define NCH     (NCODE / CCH)      // 16
#define RSTR    144                // padded smem row stride (bytes) for 128B rows

// smem offsets (dynamic)
#define OFF_X1   0
#define OFF_X2   9216
#define OFF_X3   18432
#define OFF_W1   27648
#define OFF_W2   36864
#define OFF_W3   46080
#define OFF_SWSQ 55296
#define OFF_SXSQ 55552
#define OFF_SBI  55808
#define OFF_RED  56064
#define OFF_FLAG 56576
#define SMEM_TOTAL 56832

__device__ __align__(16) float g_wnorm[NCODE * DIM];
__device__ float g_wsq[NCODE];
__device__ __align__(16) __nv_bfloat16 g_w1[NCODE * DIM];
__device__ __align__(16) __nv_bfloat16 g_w2[NCODE * DIM];
__device__ __align__(16) __nv_bfloat16 g_w3[NCODE * DIM];
__device__ int g_counts[NCODE];
__device__ float g_partials[NBLK];
__device__ unsigned g_done;

__device__ __forceinline__ uint32_t smem_u32(const void* p) {
    uint32_t a;
    asm("{ .reg .u64 t; cvta.to.shared.u64 t, %1; cvt.u32.u64 %0, t; }" : "=r"(a) : "l"(p));
    return a;
}

#define LDSM_X4(r0, r1, r2, r3, addr) \
    asm volatile("ldmatrix.sync.aligned.m8n8.x4.shared.b16 {%0,%1,%2,%3}, [%4];" \
                 : "=r"(r0), "=r"(r1), "=r"(r2), "=r"(r3) : "r"(addr))
#define LDSM_X2(r0, r1, addr) \
    asm volatile("ldmatrix.sync.aligned.m8n8.x2.shared.b16 {%0,%1}, [%2];" \
                 : "=r"(r0), "=r"(r1) : "r"(addr))
#define MMA16816(c0, c1, c2, c3, a0, a1, a2, a3, b0, b1) \
    asm volatile("mma.sync.aligned.m16n8k16.row.col.f32.bf16.bf16.f32 " \
                 "{%0,%1,%2,%3}, {%4,%5,%6,%7}, {%8,%9}, {%0,%1,%2,%3};" \
                 : "+f"(c0), "+f"(c1), "+f"(c2), "+f"(c3) \
                 : "r"(a0), "r"(a1), "r"(a2), "r"(a3), "r"(b0), "r"(b1))

// ---------------------------------------------------------------------------
// Kernel 1: prep — zero counters, normalize codebook, bf16x3 split tables.
// ---------------------------------------------------------------------------
__global__ __launch_bounds__(128) void vq_prep(const float* __restrict__ w) {
    int r = blockIdx.x * 128 + threadIdx.x;
    if (r == 0) g_done = 0;
    if (r >= NCODE) return;
    g_counts[r] = 0;
    const float4* src = (const float4*)(w + (size_t)r * DIM);
    float v[DIM];
    float ss = 0.f;
#pragma unroll
    for (int i = 0; i < DIM / 4; i++) {
        float4 q = src[i];
        v[4*i+0] = q.x; v[4*i+1] = q.y; v[4*i+2] = q.z; v[4*i+3] = q.w;
        ss += q.x*q.x + q.y*q.y + q.z*q.z + q.w*q.w;
    }
    float inv = 1.0f / fmaxf(sqrtf(ss), 1e-12f);
    float sq = 0.f;
    float4* dst = (float4*)(g_wnorm + (size_t)r * DIM);
#pragma unroll
    for (int i = 0; i < DIM / 4; i++) {
        float4 q;
        q.x = v[4*i+0] * inv; q.y = v[4*i+1] * inv;
        q.z = v[4*i+2] * inv; q.w = v[4*i+3] * inv;
        sq += q.x*q.x + q.y*q.y + q.z*q.z + q.w*q.w;
        dst[i] = q;
        v[4*i+0] = q.x; v[4*i+1] = q.y; v[4*i+2] = q.z; v[4*i+3] = q.w;
    }
    g_wsq[r] = sq;
#pragma unroll
    for (int d = 0; d < DIM; d++) {
        float e = v[d];
        __nv_bfloat16 b1 = __float2bfloat16(e);
        float r1 = e - __bfloat162float(b1);
        __nv_bfloat16 b2 = __float2bfloat16(r1);
        float r2 = r1 - __bfloat162float(b2);
        __nv_bfloat16 b3 = __float2bfloat16(r2);
        g_w1[(size_t)r * DIM + d] = b1;
        g_w2[(size_t)r * DIM + d] = b2;
        g_w3[(size_t)r * DIM + d] = b3;
    }
}

// ---------------------------------------------------------------------------
// Kernel 2: main — warp-level bf16x3 mma.sync GEMM + argmin + outputs.
// ---------------------------------------------------------------------------
__global__ __launch_bounds__(TPB) void vq_mma(const float* __restrict__ x_in,
                                              float* __restrict__ out_q,
                                              float* __restrict__ out_idx,
                                              float* __restrict__ out_loss,
                                              float* __restrict__ out_perp) {
    extern __shared__ __align__(16) char smem[];
    const uint32_t sb = smem_u32(smem);
    const int tid  = threadIdx.x;
    const int lane = tid & 31;
    const int wid  = tid >> 5;
    const int T0   = blockIdx.x * TOKB;

    float* swsq = (float*)(smem + OFF_SWSQ);
    float* sxsq = (float*)(smem + OFF_SXSQ);
    int*   sbi  = (int*)(smem + OFF_SBI);
    float* red  = (float*)(smem + OFF_RED);
    int*   flag = (int*)(smem + OFF_FLAG);

    // ---- token prep: threads 0..63 normalize one token, bf16x3 split ----
    if (tid < TOKB) {
        const float4* a4 = (const float4*)(x_in + (size_t)(T0 + tid) * DIM);
        float v[DIM];
        float ss = 0.f;
#pragma unroll
        for (int i = 0; i < DIM / 4; i++) {
            float4 q = a4[i];
            v[4*i+0] = q.x; v[4*i+1] = q.y; v[4*i+2] = q.z; v[4*i+3] = q.w;
            ss += q.x*q.x + q.y*q.y + q.z*q.z + q.w*q.w;
        }
        float inv = 1.0f / fmaxf(sqrtf(ss), 1e-12f);
        float xsq = 0.f;
        const uint32_t rowb = (uint32_t)tid * RSTR;
#pragma unroll
        for (int d = 0; d < DIM; d += 2) {
            float e0 = v[d] * inv, e1 = v[d+1] * inv;
            xsq += e0 * e0 + e1 * e1;
            __nv_bfloat16 a0 = __float2bfloat16(e0);
            float r0 = e0 - __bfloat162float(a0);
            __nv_bfloat16 b0 = __float2bfloat16(r0);
            float s0 = r0 - __bfloat162float(b0);
            __nv_bfloat16 c0_ = __float2bfloat16(s0);
            __nv_bfloat16 a1 = __float2bfloat16(e1);
            float r1 = e1 - __bfloat162float(a1);
            __nv_bfloat16 b1 = __float2bfloat16(r1);
            float s1 = r1 - __bfloat162float(b1);
            __nv_bfloat16 c1 = __float2bfloat16(s1);
            uint32_t off = rowb + (uint32_t)(d * 2);
            *(uint32_t*)(smem + OFF_X1 + off) =
                (uint32_t)__bfloat16_as_ushort(a0) | ((uint32_t)__bfloat16_as_ushort(a1) << 16);
            *(uint32_t*)(smem + OFF_X2 + off) =
                (uint32_t)__bfloat16_as_ushort(b0) | ((uint32_t)__bfloat16_as_ushort(b1) << 16);
            *(uint32_t*)(smem + OFF_X3 + off) =
                (uint32_t)__bfloat16_as_ushort(c0_) | ((uint32_t)__bfloat16_as_ushort(c1) << 16);
        }
        sxsq[tid] = xsq;
    }
    __syncthreads();

    // ---- load whole-kernel A fragments (3 splits x 4 ksteps x 4 regs) ----
    uint32_t A[3][4][4];
    {
        const uint32_t arow = (uint32_t)((wid * 16 + (lane & 15)) * RSTR + ((lane >> 4) & 1) * 16);
        const uint32_t xoff[3] = {OFF_X1, OFF_X2, OFF_X3};
#pragma unroll
        for (int s = 0; s < 3; s++) {
            uint32_t base = sb + xoff[s] + arow;
#pragma unroll
            for (int k = 0; k < 4; k++)
                LDSM_X4(A[s][k][0], A[s][k][1], A[s][k][2], A[s][k][3], base + k * 32);
        }
    }

    float bdA = INFINITY, bdB = INFINITY;
    int   biA = 0,        biB = 0;
    const uint32_t woff[3] = {OFF_W1, OFF_W2, OFF_W3};

    for (int ch = 0; ch < NCH; ch++) {
        const int c0 = ch * CCH;
        __syncthreads();   // previous chunk's readers done
        {
            const uint4* s1 = (const uint4*)(g_w1 + (size_t)c0 * DIM);
            const uint4* s2 = (const uint4*)(g_w2 + (size_t)c0 * DIM);
            const uint4* s3 = (const uint4*)(g_w3 + (size_t)c0 * DIM);
#pragma unroll
            for (int it = 0; it < 4; it++) {          // 512 uint4 per split
                int idx = it * TPB + tid;
                uint32_t doff = (uint32_t)((idx >> 3) * RSTR + (idx & 7) * 16);
                *(uint4*)(smem + OFF_W1 + doff) = s1[idx];
                *(uint4*)(smem + OFF_W2 + doff) = s2[idx];
                *(uint4*)(smem + OFF_W3 + doff) = s3[idx];
            }
            if (tid < CCH) swsq[tid] = g_wsq[c0 + tid];
        }
        __syncthreads();

        const uint32_t brow = (uint32_t)((lane & 7) * RSTR + ((lane >> 3) & 1) * 16);
#pragma unroll
        for (int nt = 0; nt < 8; nt++) {
            float c0f = 0.f, c1f = 0.f, c2f = 0.f, c3f = 0.f;
            const uint32_t bbase = (uint32_t)(nt * 8 * RSTR) + brow;
#pragma unroll
            for (int k = 0; k < 4; k++) {
                uint32_t b10, b11, b20, b21, b30, b31;
                LDSM_X2(b10, b11, sb + woff[0] + bbase + k * 32);
                LDSM_X2(b20, b21, sb + woff[1] + bbase + k * 32);
                LDSM_X2(b30, b31, sb + woff[2] + bbase + k * 32);
                // 6 split products: 11, 12, 21, 22, 13, 31
                MMA16816(c0f,c1f,c2f,c3f, A[0][k][0],A[0][k][1],A[0][k][2],A[0][k][3], b10,b11);
                MMA16816(c0f,c1f,c2f,c3f, A[0][k][0],A[0][k][1],A[0][k][2],A[0][k][3], b20,b21);
                MMA16816(c0f,c1f,c2f,c3f, A[1][k][0],A[1][k][1],A[1][k][2],A[1][k][3], b10,b11);
                MMA16816(c0f,c1f,c2f,c3f, A[1][k][0],A[1][k][1],A[1][k][2],A[1][k][3], b20,b21);
                MMA16816(c0f,c1f,c2f,c3f, A[0][k][0],A[0][k][1],A[0][k][2],A[0][k][3], b30,b31);
                MMA16816(c0f,c1f,c2f,c3f, A[2][k][0],A[2][k][1],A[2][k][2],A[2][k][3], b10,b11);
            }
            // scores: lane covers rows (lane>>2, +8), cols nt*8 + (lane&3)*2 +{0,1}
            int cb = c0 + nt * 8 + (lane & 3) * 2;
            float w0 = swsq[cb - c0], w1 = swsq[cb - c0 + 1];
            float s0 = fmaf(-2.0f, c0f, w0);
            float s1 = fmaf(-2.0f, c1f, w1);
            float s2 = fmaf(-2.0f, c2f, w0);
            float s3 = fmaf(-2.0f, c3f, w1);
            if (s0 < bdA) { bdA = s0; biA = cb; }
            if (s1 < bdA) { bdA = s1; biA = cb + 1; }
            if (s2 < bdB) { bdB = s2; biB = cb; }
            if (s3 < bdB) { bdB = s3; biB = cb + 1; }
        }
    }

    // ---- cross-lane merge within quad (lex (val,idx) == first-min) ----
#pragma unroll
    for (int d = 1; d <= 2; d <<= 1) {
        float ov = __shfl_xor_sync(0xffffffffu, bdA, d);
        int   oi = __shfl_xor_sync(0xffffffffu, biA, d);
        if (ov < bdA || (ov == bdA && oi < biA)) { bdA = ov; biA = oi; }
        float ov2 = __shfl_xor_sync(0xffffffffu, bdB, d);
        int   oi2 = __shfl_xor_sync(0xffffffffu, biB, d);
        if (ov2 < bdB || (ov2 == bdB && oi2 < biB)) { bdB = ov2; biB = oi2; }
    }

    red[tid] = 0.f;
    __syncthreads();

    if ((lane & 3) == 0) {
        int rowA = lane >> 2;                 // 0..7
        int tA = wid * 16 + rowA;             // block-local token
        int tB = tA + 8;
        sbi[tA] = biA;
        sbi[tB] = biB;
        out_idx[T0 + tA] = (float)biA;
        out_idx[T0 + tB] = (float)biB;
        atomicAdd(&g_counts[biA], 1);
        atomicAdd(&g_counts[biB], 1);
        red[tA] = sxsq[tA] + bdA;             // ||q-x||^2 = xsq + (wsq - 2 dot)
        red[tB] = sxsq[tB] + bdB;
    }
    __syncthreads();

    // ---- coalesced quantized gather/store (out_q only 4B-aligned) ----
#pragma unroll 4
    for (int it = 0; it < (TOKB * DIM) / TPB; it++) {    // 32
        int f = it * TPB + tid;
        int tok = f >> 6, lanec = f & 63;
        out_q[(size_t)T0 * DIM + f] = g_wnorm[(size_t)sbi[tok] * DIM + lanec];
    }

    // ---- deterministic per-block loss partial (red[64..127] are 0) ----
#pragma unroll
    for (int s = TPB / 2; s > 0; s >>= 1) {
        if (tid < s) red[tid] += red[tid + s];
        __syncthreads();
    }
    if (tid == 0) {
        g_partials[blockIdx.x] = red[0];
        __threadfence();
        unsigned v = atomicAdd(&g_done, 1u);
        *flag = (v == NBLK - 1) ? 1 : 0;
    }
    __syncthreads();

    // ---- last block: finalize loss + perplexity (fixed order) ----
    if (*flag) {
        __threadfence();
        float e = 0.f;
#pragma unroll
        for (int j = 0; j < NCODE / TPB; j++) {          // 8
            int c = __ldcg(&g_counts[tid * (NCODE / TPB) + j]);
            float p = (float)c * (1.0f / (float)N_TOK);
            e += p * logf(p + 1e-10f);
        }
        red[tid] = e;
        __syncthreads();
#pragma unroll
        for (int s = TPB / 2; s > 0; s >>= 1) {
            if (tid < s) red[tid] += red[tid + s];
            __syncthreads();
        }
        if (tid == 0) *out_perp = expf(-red[0]);
        __syncthreads();

        float l = 0.f;
#pragma unroll
        for (int j = 0; j < NBLK / TPB; j++)             // 8
            l += __ldcg(&g_partials[tid * (NBLK / TPB) + j]);
        red[tid] = l;
        __syncthreads();
#pragma unroll
        for (int s = TPB / 2; s > 0; s >>= 1) {
            if (tid < s) red[tid] += red[tid + s];
            __syncthreads();
        }
        if (tid == 0)
            *out_loss = 1.25f * (red[0] / (float)((long long)N_TOK * DIM));
    }
}

// ---------------------------------------------------------------------------
extern "C" void kernel_launch(void* const* d_in, const int* in_sizes, int n_in,
                              void* d_out, int out_size) {
    const float* x = (const float*)d_in[0];
    const float* w = (const float*)d_in[1];
    if (n_in >= 2 && in_sizes[0] < in_sizes[1]) {
        x = (const float*)d_in[1];
        w = (const float*)d_in[0];
    }

    float* out = (float*)d_out;
    const long long ND = (long long)N_TOK * DIM;
    float* out_loss = out;
    float* out_q    = out + 1;
    float* out_perp = out + 1 + ND;
    float* out_idx  = out + 2 + ND;

    cudaFuncSetAttribute(vq_mma, cudaFuncAttributeMaxDynamicSharedMemorySize, SMEM_TOTAL);

    vq_prep<<<8, 128>>>(w);
    vq_mma<<<NBLK, TPB, SMEM_TOTAL>>>(x, out_q, out_idx, out_loss, out_perp);
}

// round 12
// speedup vs baseline: 1.7512x; 1.0290x over previous
#include <cuda_runtime.h>
#include <cuda_bf16.h>
#include <math.h>
#include <cstdint>

// VectorQuantizer via mma.sync (HMMA) bf16x3-split GEMM.
// inputs [16,4096,64] f32, weight [1024,64] f32.
// Output (f32): [loss(1) | quantized(65536*64) | perplexity(1) | indices(65536)]
// out+1 only 4B-aligned -> scalar stores into out_q.

#define N_TOK   65536
#define DIM     64
#define NCODE   1024
#define TPB     128
#define TOKB    64
#define NBLK    (N_TOK / TOKB)     // 1024
#define CCH     64                 // codes per chunk
#define NCH     (NCODE / CCH)      // 16
#define RSTR    144                // padded smem row stride (bytes)

// smem offsets (dynamic)
#define OFF_X1   0
#define OFF_X2   9216
#define OFF_X3   18432
#define OFF_W1   27648
#define OFF_W2   36864
#define OFF_W3   46080
#define OFF_SWSQ 55296
#define OFF_SXSQ 55552
#define OFF_SBI  55808
#define OFF_RED  56064
#define OFF_FLAG 56576
#define SMEM_TOTAL 56832

__device__ __align__(16) float g_wnorm[NCODE * DIM];
__device__ float g_wsq[NCODE];
__device__ __align__(16) __nv_bfloat16 g_w1[NCODE * DIM];
__device__ __align__(16) __nv_bfloat16 g_w2[NCODE * DIM];
__device__ __align__(16) __nv_bfloat16 g_w3[NCODE * DIM];
__device__ int g_counts[NCODE];
__device__ float g_partials[NBLK];
__device__ unsigned g_done;

__device__ __forceinline__ uint32_t smem_u32(const void* p) {
    uint32_t a;
    asm("{ .reg .u64 t; cvta.to.shared.u64 t, %1; cvt.u32.u64 %0, t; }" : "=r"(a) : "l"(p));
    return a;
}

#define LDSM_X4(r0, r1, r2, r3, addr) \
    asm volatile("ldmatrix.sync.aligned.m8n8.x4.shared.b16 {%0,%1,%2,%3}, [%4];" \
                 : "=r"(r0), "=r"(r1), "=r"(r2), "=r"(r3) : "r"(addr))
#define MMA16816(c, a0, a1, a2, a3, b0, b1) \
    asm volatile("mma.sync.aligned.m16n8k16.row.col.f32.bf16.bf16.f32 " \
                 "{%0,%1,%2,%3}, {%4,%5,%6,%7}, {%8,%9}, {%0,%1,%2,%3};" \
                 : "+f"((c)[0]), "+f"((c)[1]), "+f"((c)[2]), "+f"((c)[3]) \
                 : "r"(a0), "r"(a1), "r"(a2), "r"(a3), "r"(b0), "r"(b1))

// ---------------------------------------------------------------------------
// Kernel 1: prep — zero counters, normalize codebook, bf16x3 split tables.
// ---------------------------------------------------------------------------
__global__ __launch_bounds__(128) void vq_prep(const float* __restrict__ w) {
    int r = blockIdx.x * 128 + threadIdx.x;
    if (r == 0) g_done = 0;
    if (r >= NCODE) return;
    g_counts[r] = 0;
    const float4* src = (const float4*)(w + (size_t)r * DIM);
    float v[DIM];
    float ss = 0.f;
#pragma unroll
    for (int i = 0; i < DIM / 4; i++) {
        float4 q = src[i];
        v[4*i+0] = q.x; v[4*i+1] = q.y; v[4*i+2] = q.z; v[4*i+3] = q.w;
        ss += q.x*q.x + q.y*q.y + q.z*q.z + q.w*q.w;
    }
    float inv = 1.0f / fmaxf(sqrtf(ss), 1e-12f);
    float sq = 0.f;
    float4* dst = (float4*)(g_wnorm + (size_t)r * DIM);
#pragma unroll
    for (int i = 0; i < DIM / 4; i++) {
        float4 q;
        q.x = v[4*i+0] * inv; q.y = v[4*i+1] * inv;
        q.z = v[4*i+2] * inv; q.w = v[4*i+3] * inv;
        sq += q.x*q.x + q.y*q.y + q.z*q.z + q.w*q.w;
        dst[i] = q;
        v[4*i+0] = q.x; v[4*i+1] = q.y; v[4*i+2] = q.z; v[4*i+3] = q.w;
    }
    g_wsq[r] = sq;
#pragma unroll
    for (int d = 0; d < DIM; d++) {
        float e = v[d];
        __nv_bfloat16 b1 = __float2bfloat16(e);
        float r1 = e - __bfloat162float(b1);
        __nv_bfloat16 b2 = __float2bfloat16(r1);
        float r2 = r1 - __bfloat162float(b2);
        __nv_bfloat16 b3 = __float2bfloat16(r2);
        g_w1[(size_t)r * DIM + d] = b1;
        g_w2[(size_t)r * DIM + d] = b2;
        g_w3[(size_t)r * DIM + d] = b3;
    }
}

// ---------------------------------------------------------------------------
// Kernel 2: main — warp-level bf16x3 mma.sync GEMM, dual n-subtile ILP.
// ---------------------------------------------------------------------------
__global__ __launch_bounds__(TPB) void vq_mma(const float* __restrict__ x_in,
                                              float* __restrict__ out_q,
                                              float* __restrict__ out_idx,
                                              float* __restrict__ out_loss,
                                              float* __restrict__ out_perp) {
    extern __shared__ __align__(16) char smem[];
    const uint32_t sb = smem_u32(smem);
    const int tid  = threadIdx.x;
    const int lane = tid & 31;
    const int wid  = tid >> 5;
    const int T0   = blockIdx.x * TOKB;

    float* swsq = (float*)(smem + OFF_SWSQ);
    float* sxsq = (float*)(smem + OFF_SXSQ);
    int*   sbi  = (int*)(smem + OFF_SBI);
    float* red  = (float*)(smem + OFF_RED);
    int*   flag = (int*)(smem + OFF_FLAG);

    // ---- token prep: threads 0..63 normalize one token, bf16x3 split ----
    if (tid < TOKB) {
        const float4* a4 = (const float4*)(x_in + (size_t)(T0 + tid) * DIM);
        float v[DIM];
        float ss = 0.f;
#pragma unroll
        for (int i = 0; i < DIM / 4; i++) {
            float4 q = a4[i];
            v[4*i+0] = q.x; v[4*i+1] = q.y; v[4*i+2] = q.z; v[4*i+3] = q.w;
            ss += q.x*q.x + q.y*q.y + q.z*q.z + q.w*q.w;
        }
        float inv = 1.0f / fmaxf(sqrtf(ss), 1e-12f);
        float xsq = 0.f;
        const uint32_t rowb = (uint32_t)tid * RSTR;
#pragma unroll
        for (int d = 0; d < DIM; d += 2) {
            float e0 = v[d] * inv, e1 = v[d+1] * inv;
            xsq += e0 * e0 + e1 * e1;
            __nv_bfloat16 a0 = __float2bfloat16(e0);
            float r0 = e0 - __bfloat162float(a0);
            __nv_bfloat16 b0 = __float2bfloat16(r0);
            float s0 = r0 - __bfloat162float(b0);
            __nv_bfloat16 c0_ = __float2bfloat16(s0);
            __nv_bfloat16 a1 = __float2bfloat16(e1);
            float r1 = e1 - __bfloat162float(a1);
            __nv_bfloat16 b1 = __float2bfloat16(r1);
            float s1 = r1 - __bfloat162float(b1);
            __nv_bfloat16 c1 = __float2bfloat16(s1);
            uint32_t off = rowb + (uint32_t)(d * 2);
            *(uint32_t*)(smem + OFF_X1 + off) =
                (uint32_t)__bfloat16_as_ushort(a0) | ((uint32_t)__bfloat16_as_ushort(a1) << 16);
            *(uint32_t*)(smem + OFF_X2 + off) =
                (uint32_t)__bfloat16_as_ushort(b0) | ((uint32_t)__bfloat16_as_ushort(b1) << 16);
            *(uint32_t*)(smem + OFF_X3 + off) =
                (uint32_t)__bfloat16_as_ushort(c0_) | ((uint32_t)__bfloat16_as_ushort(c1) << 16);
        }
        sxsq[tid] = xsq;
    }
    __syncthreads();

    // ---- load whole-kernel A fragments (3 splits x 4 ksteps x 4 regs) ----
    uint32_t A[3][4][4];
    {
        const uint32_t arow = (uint32_t)((wid * 16 + (lane & 15)) * RSTR + ((lane >> 4) & 1) * 16);
        const uint32_t xoff[3] = {OFF_X1, OFF_X2, OFF_X3};
#pragma unroll
        for (int s = 0; s < 3; s++) {
            uint32_t base = sb + xoff[s] + arow;
#pragma unroll
            for (int k = 0; k < 4; k++)
                LDSM_X4(A[s][k][0], A[s][k][1], A[s][k][2], A[s][k][3], base + k * 32);
        }
    }

    float bdA = INFINITY, bdB = INFINITY;
    int   biA = 0,        biB = 0;

    // B ldmatrix.x4 lane addressing (matrix m = lane>>3):
    //   m0 = codes 0-7, k 0-7    -> (lane&7)*RSTR
    //   m1 = codes 0-7, k 8-15   -> +16
    //   m2 = codes 8-15, k 0-7   -> +8*RSTR
    //   m3 = codes 8-15, k 8-15  -> +8*RSTR+16
    const uint32_t brow = (uint32_t)((lane & 7) * RSTR + ((lane >> 3) & 1) * 16
                                     + ((lane >> 4) & 1) * (8 * RSTR));

    for (int ch = 0; ch < NCH; ch++) {
        const int c0 = ch * CCH;
        __syncthreads();   // previous chunk's readers done
        {
            const uint4* s1 = (const uint4*)(g_w1 + (size_t)c0 * DIM);
            const uint4* s2 = (const uint4*)(g_w2 + (size_t)c0 * DIM);
            const uint4* s3 = (const uint4*)(g_w3 + (size_t)c0 * DIM);
#pragma unroll
            for (int it = 0; it < 4; it++) {          // 512 uint4 per split
                int idx = it * TPB + tid;
                uint32_t doff = (uint32_t)((idx >> 3) * RSTR + (idx & 7) * 16);
                *(uint4*)(smem + OFF_W1 + doff) = s1[idx];
                *(uint4*)(smem + OFF_W2 + doff) = s2[idx];
                *(uint4*)(smem + OFF_W3 + doff) = s3[idx];
            }
            if (tid < CCH) swsq[tid] = g_wsq[c0 + tid];
        }
        __syncthreads();

#pragma unroll
        for (int nt = 0; nt < 4; nt++) {              // 16 codes per iter
            float cA[4] = {0.f, 0.f, 0.f, 0.f};       // codes +0..7
            float cB[4] = {0.f, 0.f, 0.f, 0.f};       // codes +8..15
            const uint32_t bbase = (uint32_t)(nt * 16 * RSTR) + brow;
#pragma unroll
            for (int k = 0; k < 4; k++) {
                uint32_t b1[4], b2[4], b3[4];
                LDSM_X4(b1[0], b1[1], b1[2], b1[3], sb + OFF_W1 + bbase + k * 32);
                LDSM_X4(b2[0], b2[1], b2[2], b2[3], sb + OFF_W2 + bbase + k * 32);
                LDSM_X4(b3[0], b3[1], b3[2], b3[3], sb + OFF_W3 + bbase + k * 32);
                // 6 split products (11,12,21,22,13,31), 2 independent chains
                MMA16816(cA, A[0][k][0],A[0][k][1],A[0][k][2],A[0][k][3], b1[0],b1[1]);
                MMA16816(cB, A[0][k][0],A[0][k][1],A[0][k][2],A[0][k][3], b1[2],b1[3]);
                MMA16816(cA, A[0][k][0],A[0][k][1],A[0][k][2],A[0][k][3], b2[0],b2[1]);
                MMA16816(cB, A[0][k][0],A[0][k][1],A[0][k][2],A[0][k][3], b2[2],b2[3]);
                MMA16816(cA, A[1][k][0],A[1][k][1],A[1][k][2],A[1][k][3], b1[0],b1[1]);
                MMA16816(cB, A[1][k][0],A[1][k][1],A[1][k][2],A[1][k][3], b1[2],b1[3]);
                MMA16816(cA, A[1][k][0],A[1][k][1],A[1][k][2],A[1][k][3], b2[0],b2[1]);
                MMA16816(cB, A[1][k][0],A[1][k][1],A[1][k][2],A[1][k][3], b2[2],b2[3]);
                MMA16816(cA, A[0][k][0],A[0][k][1],A[0][k][2],A[0][k][3], b3[0],b3[1]);
                MMA16816(cB, A[0][k][0],A[0][k][1],A[0][k][2],A[0][k][3], b3[2],b3[3]);
                MMA16816(cA, A[2][k][0],A[2][k][1],A[2][k][2],A[2][k][3], b1[0],b1[1]);
                MMA16816(cB, A[2][k][0],A[2][k][1],A[2][k][2],A[2][k][3], b1[2],b1[3]);
            }
            // scores: rows (lane>>2) and +8; cols cb..cb+1 (subtile A), +8 (B)
            int cb = c0 + nt * 16 + (lane & 3) * 2;
            {
                float w0 = swsq[cb - c0], w1 = swsq[cb - c0 + 1];
                float s0 = fmaf(-2.0f, cA[0], w0);
                float s1 = fmaf(-2.0f, cA[1], w1);
                float s2 = fmaf(-2.0f, cA[2], w0);
                float s3 = fmaf(-2.0f, cA[3], w1);
                if (s0 < bdA) { bdA = s0; biA = cb; }
                if (s1 < bdA) { bdA = s1; biA = cb + 1; }
                if (s2 < bdB) { bdB = s2; biB = cb; }
                if (s3 < bdB) { bdB = s3; biB = cb + 1; }
            }
            {
                float w0 = swsq[cb - c0 + 8], w1 = swsq[cb - c0 + 9];
                float s0 = fmaf(-2.0f, cB[0], w0);
                float s1 = fmaf(-2.0f, cB[1], w1);
                float s2 = fmaf(-2.0f, cB[2], w0);
                float s3 = fmaf(-2.0f, cB[3], w1);
                if (s0 < bdA) { bdA = s0; biA = cb + 8; }
                if (s1 < bdA) { bdA = s1; biA = cb + 9; }
                if (s2 < bdB) { bdB = s2; biB = cb + 8; }
                if (s3 < bdB) { bdB = s3; biB = cb + 9; }
            }
        }
    }

    // ---- cross-lane merge within quad (lex (val,idx) == first-min) ----
#pragma unroll
    for (int d = 1; d <= 2; d <<= 1) {
        float ov = __shfl_xor_sync(0xffffffffu, bdA, d);
        int   oi = __shfl_xor_sync(0xffffffffu, biA, d);
        if (ov < bdA || (ov == bdA && oi < biA)) { bdA = ov; biA = oi; }
        float ov2 = __shfl_xor_sync(0xffffffffu, bdB, d);
        int   oi2 = __shfl_xor_sync(0xffffffffu, biB, d);
        if (ov2 < bdB || (ov2 == bdB && oi2 < biB)) { bdB = ov2; biB = oi2; }
    }

    red[tid] = 0.f;
    __syncthreads();

    if ((lane & 3) == 0) {
        int rowA = lane >> 2;                 // 0..7
        int tA = wid * 16 + rowA;             // block-local token
        int tB = tA + 8;
        sbi[tA] = biA;
        sbi[tB] = biB;
        out_idx[T0 + tA] = (float)biA;
        out_idx[T0 + tB] = (float)biB;
        atomicAdd(&g_counts[biA], 1);
        atomicAdd(&g_counts[biB], 1);
        red[tA] = sxsq[tA] + bdA;             // ||q-x||^2 = xsq + (wsq - 2 dot)
        red[tB] = sxsq[tB] + bdB;
    }
    __syncthreads();

    // ---- coalesced quantized gather/store (out_q only 4B-aligned) ----
#pragma unroll 4
    for (int it = 0; it < (TOKB * DIM) / TPB; it++) {    // 32
        int f = it * TPB + tid;
        int tok = f >> 6, lanec = f & 63;
        out_q[(size_t)T0 * DIM + f] = g_wnorm[(size_t)sbi[tok] * DIM + lanec];
    }

    // ---- deterministic per-block loss partial (red[64..127] are 0) ----
#pragma unroll
    for (int s = TPB / 2; s > 0; s >>= 1) {
        if (tid < s) red[tid] += red[tid + s];
        __syncthreads();
    }
    if (tid == 0) {
        g_partials[blockIdx.x] = red[0];
        __threadfence();
        unsigned v = atomicAdd(&g_done, 1u);
        *flag = (v == NBLK - 1) ? 1 : 0;
    }
    __syncthreads();

    // ---- last block: finalize loss + perplexity (fixed order) ----
    if (*flag) {
        __threadfence();
        float e = 0.f;
#pragma unroll
        for (int j = 0; j < NCODE / TPB; j++) {          // 8
            int c = __ldcg(&g_counts[tid * (NCODE / TPB) + j]);
            float p = (float)c * (1.0f / (float)N_TOK);
            e += p * logf(p + 1e-10f);
        }
        red[tid] = e;
        __syncthreads();
#pragma unroll
        for (int s = TPB / 2; s > 0; s >>= 1) {
            if (tid < s) red[tid] += red[tid + s];
            __syncthreads();
        }
        if (tid == 0) *out_perp = expf(-red[0]);
        __syncthreads();

        float l = 0.f;
#pragma unroll
        for (int j = 0; j < NBLK / TPB; j++)             // 8
            l += __ldcg(&g_partials[tid * (NBLK / TPB) + j]);
        red[tid] = l;
        __syncthreads();
#pragma unroll
        for (int s = TPB / 2; s > 0; s >>= 1) {
            if (tid < s) red[tid] += red[tid + s];
            __syncthreads();
        }
        if (tid == 0)
            *out_loss = 1.25f * (red[0] / (float)((long long)N_TOK * DIM));
    }
}

// ---------------------------------------------------------------------------
extern "C" void kernel_launch(void* const* d_in, const int* in_sizes, int n_in,
                              void* d_out, int out_size) {
    const float* x = (const float*)d_in[0];
    const float* w = (const float*)d_in[1];
    if (n_in >= 2 && in_sizes[0] < in_sizes[1]) {
        x = (const float*)d_in[1];
        w = (const float*)d_in[0];
    }

    float* out = (float*)d_out;
    const long long ND = (long long)N_TOK * DIM;
    float* out_loss = out;
    float* out_q    = out + 1;
    float* out_perp = out + 1 + ND;
    float* out_idx  = out + 2 + ND;

    cudaFuncSetAttribute(vq_mma, cudaFuncAttributeMaxDynamicSharedMemorySize, SMEM_TOTAL);

    vq_prep<<<8, 128>>>(w);
    vq_mma<<<NBLK, TPB, SMEM_TOTAL>>>(x, out_q, out_idx, out_loss, out_perp);
}

// round 13
// speedup vs baseline: 2.4998x; 1.4275x over previous
#include <cuda_runtime.h>
#include <cuda_fp16.h>
#include <math.h>
#include <cstdint>

// VectorQuantizer via mma.sync fp16x2-split GEMM (Markidis 4-product).
// inputs [16,4096,64] f32, weight [1024,64] f32.
// Output (f32): [loss(1) | quantized(65536*64) | perplexity(1) | indices(65536)]
// out+1 only 4B-aligned -> scalar stores into out_q.

#define N_TOK   65536
#define DIM     64
#define NCODE   1024
#define TPB     128
#define TOKB    64
#define NBLK    (N_TOK / TOKB)     // 1024
#define CCH     64                 // codes per chunk
#define NCH     (NCODE / CCH)      // 16
#define RSTR    144                // padded smem row stride (bytes)

// smem offsets (dynamic)
#define OFF_X1   0
#define OFF_X2   9216
#define OFF_W1   18432
#define OFF_W2   27648
#define OFF_SWSQ 36864
#define OFF_SXSQ 37120
#define OFF_SBI  37376
#define OFF_RED  37632
#define OFF_FLAG 38144
#define SMEM_TOTAL 38400

__device__ __align__(16) float g_wnorm[NCODE * DIM];
__device__ float g_wsq[NCODE];
__device__ __align__(16) __half g_w1[NCODE * DIM];
__device__ __align__(16) __half g_w2[NCODE * DIM];
__device__ int g_counts[NCODE];
__device__ float g_partials[NBLK];
__device__ unsigned g_done;

__device__ __forceinline__ uint32_t smem_u32(const void* p) {
    uint32_t a;
    asm("{ .reg .u64 t; cvta.to.shared.u64 t, %1; cvt.u32.u64 %0, t; }" : "=r"(a) : "l"(p));
    return a;
}

#define LDSM_X4(r0, r1, r2, r3, addr) \
    asm volatile("ldmatrix.sync.aligned.m8n8.x4.shared.b16 {%0,%1,%2,%3}, [%4];" \
                 : "=r"(r0), "=r"(r1), "=r"(r2), "=r"(r3) : "r"(addr))
#define MMA16816(c, a0, a1, a2, a3, b0, b1) \
    asm volatile("mma.sync.aligned.m16n8k16.row.col.f32.f16.f16.f32 " \
                 "{%0,%1,%2,%3}, {%4,%5,%6,%7}, {%8,%9}, {%0,%1,%2,%3};" \
                 : "+f"((c)[0]), "+f"((c)[1]), "+f"((c)[2]), "+f"((c)[3]) \
                 : "r"(a0), "r"(a1), "r"(a2), "r"(a3), "r"(b0), "r"(b1))

// ---------------------------------------------------------------------------
// Kernel 1: prep — zero counters, normalize codebook, fp16x2 split tables.
// ---------------------------------------------------------------------------
__global__ __launch_bounds__(128) void vq_prep(const float* __restrict__ w) {
    int r = blockIdx.x * 128 + threadIdx.x;
    if (r == 0) g_done = 0;
    if (r >= NCODE) return;
    g_counts[r] = 0;
    const float4* src = (const float4*)(w + (size_t)r * DIM);
    float v[DIM];
    float ss = 0.f;
#pragma unroll
    for (int i = 0; i < DIM / 4; i++) {
        float4 q = src[i];
        v[4*i+0] = q.x; v[4*i+1] = q.y; v[4*i+2] = q.z; v[4*i+3] = q.w;
        ss += q.x*q.x + q.y*q.y + q.z*q.z + q.w*q.w;
    }
    float inv = 1.0f / fmaxf(sqrtf(ss), 1e-12f);
    float sq = 0.f;
    float4* dst = (float4*)(g_wnorm + (size_t)r * DIM);
#pragma unroll
    for (int i = 0; i < DIM / 4; i++) {
        float4 q;
        q.x = v[4*i+0] * inv; q.y = v[4*i+1] * inv;
        q.z = v[4*i+2] * inv; q.w = v[4*i+3] * inv;
        sq += q.x*q.x + q.y*q.y + q.z*q.z + q.w*q.w;
        dst[i] = q;
        v[4*i+0] = q.x; v[4*i+1] = q.y; v[4*i+2] = q.z; v[4*i+3] = q.w;
    }
    g_wsq[r] = sq;
#pragma unroll
    for (int d = 0; d < DIM; d++) {
        float e = v[d];
        __half h1 = __float2half_rn(e);
        float r1 = e - __half2float(h1);
        __half h2 = __float2half_rn(r1);
        g_w1[(size_t)r * DIM + d] = h1;
        g_w2[(size_t)r * DIM + d] = h2;
    }
}

// ---------------------------------------------------------------------------
// Kernel 2: main — warp-level fp16x2 mma.sync GEMM, dual n-subtile ILP.
// ---------------------------------------------------------------------------
__global__ __launch_bounds__(TPB) void vq_mma(const float* __restrict__ x_in,
                                              float* __restrict__ out_q,
                                              float* __restrict__ out_idx,
                                              float* __restrict__ out_loss,
                                              float* __restrict__ out_perp) {
    extern __shared__ __align__(16) char smem[];
    const uint32_t sb = smem_u32(smem);
    const int tid  = threadIdx.x;
    const int lane = tid & 31;
    const int wid  = tid >> 5;
    const int T0   = blockIdx.x * TOKB;

    float* swsq = (float*)(smem + OFF_SWSQ);
    float* sxsq = (float*)(smem + OFF_SXSQ);
    int*   sbi  = (int*)(smem + OFF_SBI);
    float* red  = (float*)(smem + OFF_RED);
    int*   flag = (int*)(smem + OFF_FLAG);

    // ---- token prep: threads 0..63 normalize one token, fp16x2 split ----
    if (tid < TOKB) {
        const float4* a4 = (const float4*)(x_in + (size_t)(T0 + tid) * DIM);
        float v[DIM];
        float ss = 0.f;
#pragma unroll
        for (int i = 0; i < DIM / 4; i++) {
            float4 q = a4[i];
            v[4*i+0] = q.x; v[4*i+1] = q.y; v[4*i+2] = q.z; v[4*i+3] = q.w;
            ss += q.x*q.x + q.y*q.y + q.z*q.z + q.w*q.w;
        }
        float inv = 1.0f / fmaxf(sqrtf(ss), 1e-12f);
        float xsq = 0.f;
        const uint32_t rowb = (uint32_t)tid * RSTR;
#pragma unroll
        for (int d = 0; d < DIM; d += 2) {
            float e0 = v[d] * inv, e1 = v[d+1] * inv;
            xsq += e0 * e0 + e1 * e1;
            __half a0 = __float2half_rn(e0);
            __half b0 = __float2half_rn(e0 - __half2float(a0));
            __half a1 = __float2half_rn(e1);
            __half b1 = __float2half_rn(e1 - __half2float(a1));
            uint32_t off = rowb + (uint32_t)(d * 2);
            *(uint32_t*)(smem + OFF_X1 + off) =
                (uint32_t)__half_as_ushort(a0) | ((uint32_t)__half_as_ushort(a1) << 16);
            *(uint32_t*)(smem + OFF_X2 + off) =
                (uint32_t)__half_as_ushort(b0) | ((uint32_t)__half_as_ushort(b1) << 16);
        }
        sxsq[tid] = xsq;
    }
    __syncthreads();

    // ---- load whole-kernel A fragments (2 splits x 4 ksteps x 4 regs) ----
    uint32_t A[2][4][4];
    {
        const uint32_t arow = (uint32_t)((wid * 16 + (lane & 15)) * RSTR + ((lane >> 4) & 1) * 16);
        const uint32_t xoff[2] = {OFF_X1, OFF_X2};
#pragma unroll
        for (int s = 0; s < 2; s++) {
            uint32_t base = sb + xoff[s] + arow;
#pragma unroll
            for (int k = 0; k < 4; k++)
                LDSM_X4(A[s][k][0], A[s][k][1], A[s][k][2], A[s][k][3], base + k * 32);
        }
    }

    float bdA = INFINITY, bdB = INFINITY;
    int   biA = 0,        biB = 0;

    // B ldmatrix.x4 lane addressing (matrix m = lane>>3):
    //   m0 = codes 0-7, k 0-7; m1 = codes 0-7, k 8-15;
    //   m2 = codes 8-15, k 0-7; m3 = codes 8-15, k 8-15.
    const uint32_t brow = (uint32_t)((lane & 7) * RSTR + ((lane >> 3) & 1) * 16
                                     + ((lane >> 4) & 1) * (8 * RSTR));

    for (int ch = 0; ch < NCH; ch++) {
        const int c0 = ch * CCH;
        __syncthreads();   // previous chunk's readers done
        {
            const uint4* s1 = (const uint4*)(g_w1 + (size_t)c0 * DIM);
            const uint4* s2 = (const uint4*)(g_w2 + (size_t)c0 * DIM);
#pragma unroll
            for (int it = 0; it < 4; it++) {          // 512 uint4 per split
                int idx = it * TPB + tid;
                uint32_t doff = (uint32_t)((idx >> 3) * RSTR + (idx & 7) * 16);
                *(uint4*)(smem + OFF_W1 + doff) = s1[idx];
                *(uint4*)(smem + OFF_W2 + doff) = s2[idx];
            }
            if (tid < CCH) swsq[tid] = g_wsq[c0 + tid];
        }
        __syncthreads();

#pragma unroll
        for (int nt = 0; nt < 4; nt++) {              // 16 codes per iter
            float cA[4] = {0.f, 0.f, 0.f, 0.f};       // codes +0..7
            float cB[4] = {0.f, 0.f, 0.f, 0.f};       // codes +8..15
            const uint32_t bbase = (uint32_t)(nt * 16 * RSTR) + brow;
#pragma unroll
            for (int k = 0; k < 4; k++) {
                uint32_t b1[4], b2[4];
                LDSM_X4(b1[0], b1[1], b1[2], b1[3], sb + OFF_W1 + bbase + k * 32);
                LDSM_X4(b2[0], b2[1], b2[2], b2[3], sb + OFF_W2 + bbase + k * 32);
                // 4 split products (11,12,21,22), 2 independent chains
                MMA16816(cA, A[0][k][0],A[0][k][1],A[0][k][2],A[0][k][3], b1[0],b1[1]);
                MMA16816(cB, A[0][k][0],A[0][k][1],A[0][k][2],A[0][k][3], b1[2],b1[3]);
                MMA16816(cA, A[0][k][0],A[0][k][1],A[0][k][2],A[0][k][3], b2[0],b2[1]);
                MMA16816(cB, A[0][k][0],A[0][k][1],A[0][k][2],A[0][k][3], b2[2],b2[3]);
                MMA16816(cA, A[1][k][0],A[1][k][1],A[1][k][2],A[1][k][3], b1[0],b1[1]);
                MMA16816(cB, A[1][k][0],A[1][k][1],A[1][k][2],A[1][k][3], b1[2],b1[3]);
                MMA16816(cA, A[1][k][0],A[1][k][1],A[1][k][2],A[1][k][3], b2[0],b2[1]);
                MMA16816(cB, A[1][k][0],A[1][k][1],A[1][k][2],A[1][k][3], b2[2],b2[3]);
            }
            // scores: rows (lane>>2) and +8; cols cb..cb+1 (subtile A), +8 (B)
            int cb = c0 + nt * 16 + (lane & 3) * 2;
            {
                float w0 = swsq[cb - c0], w1 = swsq[cb - c0 + 1];
                float s0 = fmaf(-2.0f, cA[0], w0);
                float s1 = fmaf(-2.0f, cA[1], w1);
                float s2 = fmaf(-2.0f, cA[2], w0);
                float s3 = fmaf(-2.0f, cA[3], w1);
                if (s0 < bdA) { bdA = s0; biA = cb; }
                if (s1 < bdA) { bdA = s1; biA = cb + 1; }
                if (s2 < bdB) { bdB = s2; biB = cb; }
                if (s3 < bdB) { bdB = s3; biB = cb + 1; }
            }
            {
                float w0 = swsq[cb - c0 + 8], w1 = swsq[cb - c0 + 9];
                float s0 = fmaf(-2.0f, cB[0], w0);
                float s1 = fmaf(-2.0f, cB[1], w1);
                float s2 = fmaf(-2.0f, cB[2], w0);
                float s3 = fmaf(-2.0f, cB[3], w1);
                if (s0 < bdA) { bdA = s0; biA = cb + 8; }
                if (s1 < bdA) { bdA = s1; biA = cb + 9; }
                if (s2 < bdB) { bdB = s2; biB = cb + 8; }
                if (s3 < bdB) { bdB = s3; biB = cb + 9; }
            }
        }
    }

    // ---- cross-lane merge within quad (lex (val,idx) == first-min) ----
#pragma unroll
    for (int d = 1; d <= 2; d <<= 1) {
        float ov = __shfl_xor_sync(0xffffffffu, bdA, d);
        int   oi = __shfl_xor_sync(0xffffffffu, biA, d);
        if (ov < bdA || (ov == bdA && oi < biA)) { bdA = ov; biA = oi; }
        float ov2 = __shfl_xor_sync(0xffffffffu, bdB, d);
        int   oi2 = __shfl_xor_sync(0xffffffffu, biB, d);
        if (ov2 < bdB || (ov2 == bdB && oi2 < biB)) { bdB = ov2; biB = oi2; }
    }

    red[tid] = 0.f;
    __syncthreads();

    if ((lane & 3) == 0) {
        int rowA = lane >> 2;                 // 0..7
        int tA = wid * 16 + rowA;             // block-local token
        int tB = tA + 8;
        sbi[tA] = biA;
        sbi[tB] = biB;
        out_idx[T0 + tA] = (float)biA;
        out_idx[T0 + tB] = (float)biB;
        atomicAdd(&g_counts[biA], 1);
        atomicAdd(&g_counts[biB], 1);
        red[tA] = sxsq[tA] + bdA;             // ||q-x||^2 = xsq + (wsq - 2 dot)
        red[tB] = sxsq[tB] + bdB;
    }
    __syncthreads();

    // ---- coalesced quantized gather/store (out_q only 4B-aligned) ----
#pragma unroll 4
    for (int it = 0; it < (TOKB * DIM) / TPB; it++) {    // 32
        int f = it * TPB + tid;
        int tok = f >> 6, lanec = f & 63;
        out_q[(size_t)T0 * DIM + f] = g_wnorm[(size_t)sbi[tok] * DIM + lanec];
    }

    // ---- deterministic per-block loss partial (red[64..127] are 0) ----
#pragma unroll
    for (int s = TPB / 2; s > 0; s >>= 1) {
        if (tid < s) red[tid] += red[tid + s];
        __syncthreads();
    }
    if (tid == 0) {
        g_partials[blockIdx.x] = red[0];
        __threadfence();
        unsigned v = atomicAdd(&g_done, 1u);
        *flag = (v == NBLK - 1) ? 1 : 0;
    }
    __syncthreads();

    // ---- last block: finalize loss + perplexity (fixed order) ----
    if (*flag) {
        __threadfence();
        float e = 0.f;
#pragma unroll
        for (int j = 0; j < NCODE / TPB; j++) {          // 8
            int c = __ldcg(&g_counts[tid * (NCODE / TPB) + j]);
            float p = (float)c * (1.0f / (float)N_TOK);
            e += p * logf(p + 1e-10f);
        }
        red[tid] = e;
        __syncthreads();
#pragma unroll
        for (int s = TPB / 2; s > 0; s >>= 1) {
            if (tid < s) red[tid] += red[tid + s];
            __syncthreads();
        }
        if (tid == 0) *out_perp = expf(-red[0]);
        __syncthreads();

        float l = 0.f;
#pragma unroll
        for (int j = 0; j < NBLK / TPB; j++)             // 8
            l += __ldcg(&g_partials[tid * (NBLK / TPB) + j]);
        red[tid] = l;
        __syncthreads();
#pragma unroll
        for (int s = TPB / 2; s > 0; s >>= 1) {
            if (tid < s) red[tid] += red[tid + s];
            __syncthreads();
        }
        if (tid == 0)
            *out_loss = 1.25f * (red[0] / (float)((long long)N_TOK * DIM));
    }
}

// ---------------------------------------------------------------------------
extern "C" void kernel_launch(void* const* d_in, const int* in_sizes, int n_in,
                              void* d_out, int out_size) {
    const float* x = (const float*)d_in[0];
    const float* w = (const float*)d_in[1];
    if (n_in >= 2 && in_sizes[0] < in_sizes[1]) {
        x = (const float*)d_in[1];
        w = (const float*)d_in[0];
    }

    float* out = (float*)d_out;
    const long long ND = (long long)N_TOK * DIM;
    float* out_loss = out;
    float* out_q    = out + 1;
    float* out_perp = out + 1 + ND;
    float* out_idx  = out + 2 + ND;

    cudaFuncSetAttribute(vq_mma, cudaFuncAttributeMaxDynamicSharedMemorySize, SMEM_TOTAL);

    vq_prep<<<8, 128>>>(w);
    vq_mma<<<NBLK, TPB, SMEM_TOTAL>>>(x, out_q, out_idx, out_loss, out_perp);
}